// round 5
// baseline (speedup 1.0000x reference)
#include <cuda_runtime.h>

// Problem constants
#define B_   32
#define TQ_  1024
#define TK_  1024
#define DK_  64
#define NTHREADS 512

// smem layout (floats): sQ[2048] | sS[32*1024] | sKV[4*4096] (2 dbl-buffers per group)
#define SS_OFF   2048
#define SKV_OFF  (SS_OFF + 32 * 1024)
#define SMEM_FLOATS (SKV_OFF + 4 * 4096)
#define SMEM_BYTES  (SMEM_FLOATS * 4)      // 200 KB

// Packed f32x2 FMA (Blackwell dual-issue fp32 path)
__device__ __forceinline__ void ffma2(float2 &d, const float2 a, const float2 b) {
    unsigned long long &dd = reinterpret_cast<unsigned long long &>(d);
    asm("fma.rn.f32x2 %0, %1, %2, %0;"
        : "+l"(dd)
        : "l"(reinterpret_cast<const unsigned long long &>(a)),
          "l"(reinterpret_cast<const unsigned long long &>(b)));
}

__device__ __forceinline__ void gbar(int g) {   // per-group named barrier (256 threads)
    asm volatile("bar.sync %0, 256;" :: "r"(g + 1) : "memory");
}

__global__ void __launch_bounds__(NTHREADS, 1)
mha_fused_kernel(const float* __restrict__ Kg, const float* __restrict__ Vg,
                 const float* __restrict__ Qg, const int* __restrict__ Mg,
                 const float* __restrict__ QMg,
                 float* __restrict__ outR, float* __restrict__ outA)
{
    extern __shared__ float sm[];
    float* sQ  = sm;
    float* sS  = sm + SS_OFF;
    float* sKV = sm + SKV_OFF;

    const int tid = threadIdx.x;
    const int b   = blockIdx.x >> 5;
    const int q0  = (blockIdx.x & 31) * 32;

    const float* gQ = Qg + ((size_t)b * TQ_ + q0) * DK_;
    const float* gK = Kg + (size_t)b * TK_ * DK_;
    const float* gV = Vg + (size_t)b * TK_ * DK_;

    const int w   = tid >> 5;       // 16 warps
    const int ln  = tid & 31;
    const int g   = w >> 3;         // group 0: even k-tiles, group 1: odd k-tiles
    const int wg  = w & 7;          // warp-in-group -> q rows 4wg..4wg+3
    const int tg  = tid & 255;      // thread-in-group
    const int kk  = ln & 7;
    const int dd  = ln >> 3;

    float* bufs = sKV + g * 8192;   // this group's two 4096-float buffers

    // ---- stage Q (once) ----
    for (int i = tid; i < 512; i += NTHREADS)
        ((float4*)sQ)[i] = ((const float4*)gQ)[i];

    // ---- prefetch this group's first K tile (tile index g) ----
    float4 pref[4];
    #pragma unroll
    for (int p = 0; p < 4; p++) {
        int idx = tg + p * 256, row = idx >> 4, c = idx & 15;
        pref[p] = *(const float4*)(gK + (size_t)g * 4096 + row * 64 + c * 4);
    }
    __syncthreads();   // sQ visible

    // ---- Q in registers: 4 rows x 16-d slice ----
    float2 q2[4][8];
    #pragma unroll
    for (int i = 0; i < 4; i++) {
        #pragma unroll
        for (int j = 0; j < 8; j++)
            q2[i][j] = *(const float2*)(sQ + (4*wg + i) * 64 + dd * 16 + 2 * j);
    }

    // swizzled read offsets: d4 = 4*dd+u, off = (d4 ^ kk) words *4B
    int uoff[4];
    #pragma unroll
    for (int u = 0; u < 4; u++) uoff[u] = ((4 * dd + u) ^ kk) << 2;

    // =========================== QK^T (8 tiles per group) ===========================
    for (int it = 0; it < 8; it++) {
        const int t = 2 * it + g;                 // this group's tile
        float* kb = bufs + (it & 1) * 4096;
        #pragma unroll
        for (int p = 0; p < 4; p++) {
            int idx = tg + p * 256, row = idx >> 4, c = idx & 15;
            *(float4*)(kb + row * 64 + ((c ^ (row & 7)) << 2)) = pref[p];
        }
        gbar(g);
        if (it + 1 < 8) {
            #pragma unroll
            for (int p = 0; p < 4; p++) {
                int idx = tg + p * 256, row = idx >> 4, c = idx & 15;
                pref[p] = *(const float4*)(gK + (size_t)(t + 2) * 4096 + row * 64 + c * 4);
            }
        }
        #pragma unroll
        for (int pass = 0; pass < 2; pass++) {
            float2 acc[4][4];
            #pragma unroll
            for (int i = 0; i < 4; i++) {
                #pragma unroll
                for (int r = 0; r < 4; r++) acc[i][r] = make_float2(0.f, 0.f);
            }
            #pragma unroll
            for (int rr = 0; rr < 4; rr++) {
                const float* kbase = kb + (kk + 8 * (pass * 4 + rr)) * 64;
                #pragma unroll
                for (int u = 0; u < 4; u++) {
                    float4 kv = *(const float4*)(kbase + uoff[u]);
                    #pragma unroll
                    for (int i = 0; i < 4; i++) {
                        ffma2(acc[i][rr], q2[i][2*u],     make_float2(kv.x, kv.y));
                        ffma2(acc[i][rr], q2[i][2*u + 1], make_float2(kv.z, kv.w));
                    }
                }
            }
            #pragma unroll
            for (int i = 0; i < 4; i++) {
                float v0 = acc[i][0].x + acc[i][0].y;
                float v1 = acc[i][1].x + acc[i][1].y;
                float v2 = acc[i][2].x + acc[i][2].y;
                float v3 = acc[i][3].x + acc[i][3].y;
                v0 += __shfl_xor_sync(0xffffffffu, v0, 8);
                v0 += __shfl_xor_sync(0xffffffffu, v0, 16);
                v1 += __shfl_xor_sync(0xffffffffu, v1, 8);
                v1 += __shfl_xor_sync(0xffffffffu, v1, 16);
                v2 += __shfl_xor_sync(0xffffffffu, v2, 8);
                v2 += __shfl_xor_sync(0xffffffffu, v2, 16);
                v3 += __shfl_xor_sync(0xffffffffu, v3, 8);
                v3 += __shfl_xor_sync(0xffffffffu, v3, 16);
                float vs = (dd == 0) ? v0 : (dd == 1) ? v1 : (dd == 2) ? v2 : v3;
                sS[(4*wg + i) * 1024 + t * 64 + kk + 8 * (pass * 4 + dd)] = vs * 0.125f;
            }
        }
    }

    // ---- prefetch this group's first V tile (overlaps softmax tail) ----
    #pragma unroll
    for (int p = 0; p < 4; p++) {
        int idx = tg + p * 256, row = idx >> 4, c = idx & 15;
        pref[p] = *(const float4*)(gV + (size_t)g * 4096 + row * 64 + c * 4);
    }
    __syncthreads();   // all scores written (both groups)

    // =========================== softmax: warp w -> rows 2w, 2w+1 ===========================
    #pragma unroll 1
    for (int rr = 0; rr < 2; rr++) {
        const int q  = 2 * w + rr;
        const int qg = q0 + q;
        const int* mrow = Mg + ((size_t)b * TQ_ + qg) * TK_;
        float* srow = sS + q * TK_;
        float4 sv[8];
        unsigned mb = 0u;
        float mx = -3.0e38f;
        #pragma unroll
        for (int i = 0; i < 8; i++) {
            sv[i] = *(const float4*)(srow + i * 128 + 4 * ln);
            int4 m = *(const int4*)(mrow + i * 128 + 4 * ln);
            unsigned bits = (m.x ? 1u : 0u) | (m.y ? 2u : 0u) | (m.z ? 4u : 0u) | (m.w ? 8u : 0u);
            mb |= bits << (4 * i);
            if (!m.x) mx = fmaxf(mx, sv[i].x);
            if (!m.y) mx = fmaxf(mx, sv[i].y);
            if (!m.z) mx = fmaxf(mx, sv[i].z);
            if (!m.w) mx = fmaxf(mx, sv[i].w);
        }
        #pragma unroll
        for (int o = 16; o > 0; o >>= 1) mx = fmaxf(mx, __shfl_xor_sync(0xffffffffu, mx, o));
        float sum = 0.f;
        #pragma unroll
        for (int i = 0; i < 8; i++) {
            float p0 = ((mb >> (4*i)) & 1u) ? 0.f : __expf(sv[i].x - mx);
            float p1 = ((mb >> (4*i + 1)) & 1u) ? 0.f : __expf(sv[i].y - mx);
            float p2 = ((mb >> (4*i + 2)) & 1u) ? 0.f : __expf(sv[i].z - mx);
            float p3 = ((mb >> (4*i + 3)) & 1u) ? 0.f : __expf(sv[i].w - mx);
            sv[i] = make_float4(p0, p1, p2, p3);
            sum += (p0 + p1) + (p2 + p3);
        }
        #pragma unroll
        for (int o = 16; o > 0; o >>= 1) sum += __shfl_xor_sync(0xffffffffu, sum, o);

        const float qm = QMg[(size_t)b * TQ_ + qg];
        const bool allmask = !(sum > 0.f);        // fully-masked row -> uniform softmax
        const float scale = allmask ? 0.f : (qm / sum);
        const float uni   = qm * (1.0f / 1024.0f);
        float* arow = outA + ((size_t)b * TQ_ + qg) * TK_;
        #pragma unroll
        for (int i = 0; i < 8; i++) {
            float4 v;
            v.x = allmask ? uni : sv[i].x * scale;
            v.y = allmask ? uni : sv[i].y * scale;
            v.z = allmask ? uni : sv[i].z * scale;
            v.w = allmask ? uni : sv[i].w * scale;
            *(float4*)(srow + i * 128 + 4 * ln) = v;   // reused by PV
            *(float4*)(arow + i * 128 + 4 * ln) = v;   // attn output
        }
    }
    __syncthreads();   // scores final before PV reads cross-warp rows

    // =========================== PV (8 tiles per group, partial over k-half) ===========================
    float2 acc[4][8];
    #pragma unroll
    for (int i = 0; i < 4; i++) {
        #pragma unroll
        for (int j = 0; j < 8; j++) acc[i][j] = make_float2(0.f, 0.f);
    }

    for (int it = 0; it < 8; it++) {
        const int t = 2 * it + g;
        float* vb = bufs + (it & 1) * 4096;
        #pragma unroll
        for (int p = 0; p < 4; p++) {
            int idx = tg + p * 256, row = idx >> 4, c = idx & 15;
            *(float4*)(vb + row * 64 + ((c ^ (row & 7)) << 2)) = pref[p];
        }
        gbar(g);
        if (it + 1 < 8) {
            #pragma unroll
            for (int p = 0; p < 4; p++) {
                int idx = tg + p * 256, row = idx >> 4, c = idx & 15;
                pref[p] = *(const float4*)(gV + (size_t)(t + 2) * 4096 + row * 64 + c * 4);
            }
        }
        #pragma unroll
        for (int r = 0; r < 8; r++) {
            const int kt = kk + 8 * r;
            const float* vbase = vb + kt * 64;
            float4 vv0 = *(const float4*)(vbase + uoff[0]);
            float4 vv1 = *(const float4*)(vbase + uoff[1]);
            float4 vv2 = *(const float4*)(vbase + uoff[2]);
            float4 vv3 = *(const float4*)(vbase + uoff[3]);
            #pragma unroll
            for (int i = 0; i < 4; i++) {
                float s = sS[(4*wg + i) * 1024 + t * 64 + kt];   // broadcast LDS
                float2 s2 = make_float2(s, s);
                ffma2(acc[i][0], s2, make_float2(vv0.x, vv0.y));
                ffma2(acc[i][1], s2, make_float2(vv0.z, vv0.w));
                ffma2(acc[i][2], s2, make_float2(vv1.x, vv1.y));
                ffma2(acc[i][3], s2, make_float2(vv1.z, vv1.w));
                ffma2(acc[i][4], s2, make_float2(vv2.x, vv2.y));
                ffma2(acc[i][5], s2, make_float2(vv2.z, vv2.w));
                ffma2(acc[i][6], s2, make_float2(vv3.x, vv3.y));
                ffma2(acc[i][7], s2, make_float2(vv3.z, vv3.w));
            }
        }
    }

    // in-warp reduce over the 8 kk-lanes
    #pragma unroll
    for (int i = 0; i < 4; i++) {
        #pragma unroll
        for (int j = 0; j < 8; j++) {
            float x = acc[i][j].x, y = acc[i][j].y;
            x += __shfl_xor_sync(0xffffffffu, x, 1);
            y += __shfl_xor_sync(0xffffffffu, y, 1);
            x += __shfl_xor_sync(0xffffffffu, x, 2);
            y += __shfl_xor_sync(0xffffffffu, y, 2);
            x += __shfl_xor_sync(0xffffffffu, x, 4);
            y += __shfl_xor_sync(0xffffffffu, y, 4);
            acc[i][j] = make_float2(x, y);
        }
    }

    // cross-group reduce through smem scratch (reuse sKV[0..4095] after barrier)
    float* scratch = sKV;
    __syncthreads();   // all PV compute done; buffers reusable
    #pragma unroll
    for (int i = 0; i < 4; i++) {
        float rx = acc[i][0].x, ry = acc[i][0].y;
        #pragma unroll
        for (int j = 1; j < 8; j++) {
            if (kk == j) { rx = acc[i][j].x; ry = acc[i][j].y; }
        }
        // scratch[(g*32 + row)*64 + d], d = 16*dd + 2*kk
        *(float2*)(scratch + ((g * 32 + 4*wg + i) * 64) + 16 * dd + 2 * kk) = make_float2(rx, ry);
    }
    __syncthreads();

    // warp w sums rows 2w, 2w+1 across groups and stores
    #pragma unroll
    for (int rr = 0; rr < 2; rr++) {
        const int q = 2 * w + rr;
        float2 a0 = *(const float2*)(scratch + q * 64 + 2 * ln);
        float2 a1 = *(const float2*)(scratch + (32 + q) * 64 + 2 * ln);
        float2 r  = make_float2(a0.x + a1.x, a0.y + a1.y);
        *(float2*)(outR + ((size_t)b * TQ_ + q0 + q) * DK_ + 2 * ln) = r;
    }
}

extern "C" void kernel_launch(void* const* d_in, const int* in_sizes, int n_in,
                              void* d_out, int out_size)
{
    const float* Kg  = (const float*)d_in[0];
    const float* Vg  = (const float*)d_in[1];
    const float* Qg  = (const float*)d_in[2];
    const int*   Mg  = (const int*)d_in[3];
    const float* QMg = (const float*)d_in[4];

    float* outR = (float*)d_out;                       // result [B, TQ, DK]
    float* outA = outR + (size_t)B_ * TQ_ * DK_;       // attn   [B, TQ, TK]

    cudaFuncSetAttribute(mha_fused_kernel,
                         cudaFuncAttributeMaxDynamicSharedMemorySize, SMEM_BYTES);

    dim3 grid(B_ * 32);   // 1024 CTAs
    mha_fused_kernel<<<grid, NTHREADS, SMEM_BYTES>>>(Kg, Vg, Qg, Mg, QMg, outR, outA);
}